// round 15
// baseline (speedup 1.0000x reference)
#include <cuda_runtime.h>
#include <cuda_bf16.h>
#include <cstdint>

// ---------------------------------------------------------------------------
// Problem constants
// ---------------------------------------------------------------------------
#define NROWS 2048
#define NFEAT 128
#define TILE  128
#define PREP_BLOCKS 256           // 8 rows per block: shortest serial chain
#define MAIN_CTAS 264             // 256 tile CTAs + 8 sigma-reducer CTAs

// ---------------------------------------------------------------------------
// Device scratch (zero-initialized; no allocation allowed)
// ---------------------------------------------------------------------------
__device__ __nv_bfloat16 g_Xb[NROWS * NFEAT];        // bf16-quantized X
__device__ float g_norm[NROWS];                      // row norms of quantized X
__device__ float g_s_part[PREP_BLOCKS][NFEAT];       // per-block feature sums
__device__ float g_sumn_part[PREP_BLOCKS];           // per-block norm sums
__device__ float g_s2[8][NFEAT];                     // level-2 feature sums
__device__ float g_sn2[8];                           // level-2 norm sums
__device__ float g_c;                                // inv2s * log2(e)
__device__ int   g_ctr3;                             // sigma level-2 counter
__device__ int   g_ctr2;                             // exit counter
__device__ int   g_flag2;                            // sigma ready

// ---------------------------------------------------------------------------
// Helpers
// ---------------------------------------------------------------------------
__device__ __forceinline__ uint32_t smem_to_u32(const void* p) {
    uint32_t a;
    asm("{ .reg .u64 t; cvta.to.shared.u64 t, %1; cvt.u32.u64 %0, t; }" : "=r"(a) : "l"(p));
    return a;
}

__device__ __forceinline__ void ldmatrix_x4(uint32_t& r0, uint32_t& r1,
                                            uint32_t& r2, uint32_t& r3, uint32_t addr) {
    asm volatile("ldmatrix.sync.aligned.m8n8.x4.shared.b16 {%0,%1,%2,%3}, [%4];"
                 : "=r"(r0), "=r"(r1), "=r"(r2), "=r"(r3) : "r"(addr));
}

__device__ __forceinline__ void mma_16816(float* d, const uint32_t* a, const uint32_t* b) {
    asm volatile(
        "mma.sync.aligned.m16n8k16.row.col.f32.bf16.bf16.f32 "
        "{%0,%1,%2,%3}, {%4,%5,%6,%7}, {%8,%9}, {%0,%1,%2,%3};"
        : "+f"(d[0]), "+f"(d[1]), "+f"(d[2]), "+f"(d[3])
        : "r"(a[0]), "r"(a[1]), "r"(a[2]), "r"(a[3]), "r"(b[0]), "r"(b[1]));
}

__device__ __forceinline__ float ex2f(float x) {
    float r;
    asm("ex2.approx.ftz.f32 %0, %1;" : "=f"(r) : "f"(x));
    return r;
}

__device__ __forceinline__ void spin_until(volatile int* fp) {
    while (*fp == 0) { __nanosleep(32); }
}

// cp.async 16B, L2-coherent (.cg): GMEM -> SMEM, no register staging
#define CP16(dst_smem, src_gmem)                                                \
    asm volatile("cp.async.cg.shared.global [%0], [%1], 16;"                    \
                 :: "r"(dst_smem), "l"(src_gmem) : "memory")
#define CP_COMMIT()   asm volatile("cp.async.commit_group;" ::: "memory")
#define CP_WAIT(n)    asm volatile("cp.async.wait_group %0;" :: "n"(n) : "memory")

// ---------------------------------------------------------------------------
// Kernel 1: prep. grid 256, block 256; block handles 8 rows (warp w = row w).
// ---------------------------------------------------------------------------
__global__ void __launch_bounds__(256) prep_kernel(const float* __restrict__ X) {
    int b   = blockIdx.x;
    int tid = threadIdx.x;
    int wid = tid >> 5;
    int lid = tid & 31;

    __shared__ float ss[8][NFEAT];
    __shared__ float sn[8];

    {
        int row = b * 8 + wid;
        float4 v = reinterpret_cast<const float4*>(X + (size_t)row * NFEAT)[lid];
        __nv_bfloat16 b0 = __float2bfloat16(v.x);
        __nv_bfloat16 b1 = __float2bfloat16(v.y);
        __nv_bfloat16 b2 = __float2bfloat16(v.z);
        __nv_bfloat16 b3 = __float2bfloat16(v.w);
        __nv_bfloat162* dst =
            reinterpret_cast<__nv_bfloat162*>(g_Xb + (size_t)row * NFEAT) + lid * 2;
        dst[0] = __nv_bfloat162(b0, b1);
        dst[1] = __nv_bfloat162(b2, b3);
        // quantized values downstream (diag exactly 0 -> out = 1)
        float fx = __bfloat162float(b0), fy = __bfloat162float(b1);
        float fz = __bfloat162float(b2), fw = __bfloat162float(b3);
        float sq = fx * fx + fy * fy + fz * fz + fw * fw;
        #pragma unroll
        for (int o = 16; o > 0; o >>= 1) sq += __shfl_xor_sync(0xFFFFFFFFu, sq, o);
        if (lid == 0) { g_norm[row] = sq; sn[wid] = sq; }
        ss[wid][lid * 4 + 0] = fx;
        ss[wid][lid * 4 + 1] = fy;
        ss[wid][lid * 4 + 2] = fz;
        ss[wid][lid * 4 + 3] = fw;
    }
    __syncthreads();
    if (tid < NFEAT) {
        float t = 0.f;
        #pragma unroll
        for (int w = 0; w < 8; w++) t += ss[w][tid];
        g_s_part[b][tid] = t;
    }
    if (tid == 0) {
        float t = 0.f;
        #pragma unroll
        for (int w = 0; w < 8; w++) t += sn[w];
        g_sumn_part[b] = t;
    }
}

// ---------------------------------------------------------------------------
// Kernel 2: main. grid 264 x 256 threads (R13 GEMM geometry + cp.async pipe).
//   b <  256 : GEMM tile CTA (4x2 warps, 32x64 each, double-buffered frags)
//   b >= 256 : sigma reducer CTA; reduce -> flag2 -> exit.
// ---------------------------------------------------------------------------
#define OFF_CI  0
#define OFF_CJ  512
#define OFF_A   1024
#define OFF_B   (1024 + 32768)
#define OFF_FS  (OFF_B + 32768)
#define SMEM_TOTAL (OFF_FS + 1024)      // 67584 B -> 2 CTAs/SM

__global__ void __launch_bounds__(256, 2) gauss_main_kernel(float* __restrict__ out) {
    extern __shared__ char smem[];
    uint32_t sb = smem_to_u32(smem);
    int b   = blockIdx.x;
    int tid = threadIdx.x;
    int wid = tid >> 5;
    int lid = tid & 31;

    __shared__ float red[5];
    __shared__ int   s_last3;

    // =============== Sigma reducer CTAs (b >= 256): reduce and exit ========
    if (b >= 256) {
        int b2 = b - 256;                                      // 0..7
        float* ss2 = reinterpret_cast<float*>(smem + OFF_FS);  // [2][128]
        {
            int f = tid & 127;
            int g = tid >> 7;                                  // 0 or 1
            float sf = 0.f;
            #pragma unroll 16
            for (int p = b2 * 32 + g * 16; p < b2 * 32 + g * 16 + 16; p++)
                sf += g_s_part[p][f];
            ss2[g * NFEAT + f] = sf;
        }
        if (tid < 32) {
            float sna = g_sumn_part[b2 * 32 + tid];
            #pragma unroll
            for (int o = 16; o > 0; o >>= 1) sna += __shfl_xor_sync(0xFFFFFFFFu, sna, o);
            if (tid == 0) g_sn2[b2] = sna;
        }
        __syncthreads();
        if (tid < NFEAT)
            g_s2[b2][tid] = ss2[tid] + ss2[NFEAT + tid];
        __threadfence();
        __syncthreads();
        if (tid == 0) s_last3 = (atomicAdd(&g_ctr3, 1) == 7) ? 1 : 0;
        __syncthreads();
        if (s_last3) {
            if (tid < NFEAT) {
                float s = 0.f;
                #pragma unroll
                for (int q = 0; q < 8; q++) s += __ldcg(&g_s2[q][tid]);
                float v = s * s;
                #pragma unroll
                for (int o = 16; o > 0; o >>= 1) v += __shfl_xor_sync(0xFFFFFFFFu, v, o);
                if (lid == 0) red[wid] = v;
            }
            if (tid >= 224) {      // warp 7 sums sn2
                float sna = (lid < 8) ? __ldcg(&g_sn2[lid]) : 0.f;
                #pragma unroll
                for (int o = 4; o > 0; o >>= 1) sna += __shfl_xor_sync(0xFFFFFFFFu, sna, o);
                if (lid == 0) red[4] = sna;
            }
            __syncthreads();
            if (tid == 0) {
                float S2   = red[0] + red[1] + red[2] + red[3];
                float sumn = red[4];
                float Nf = (float)NROWS;
                float inv2s = (Nf * Nf) / (4.f * Nf * sumn - 4.f * S2);
                g_c = inv2s * 1.4426950408889634f;   // fold log2(e) for ex2
                __threadfence();
                *((volatile int*)&g_flag2) = 1;
            }
        }
        if (tid == 0) {
            if (atomicAdd(&g_ctr2, 1) == MAIN_CTAS - 1) {
                g_ctr3 = 0; g_ctr2 = 0; g_flag2 = 0;
            }
        }
        return;
    }

    // =============== GEMM tile CTA ==========================================
    int bj = b & 15;
    int bi = b >> 4;

    // cp.async both K-halves as two commit groups (no register staging)
    const char* Ag = reinterpret_cast<const char*>(g_Xb) + (size_t)bi * TILE * 256;
    const char* Bg = reinterpret_cast<const char*>(g_Xb) + (size_t)bj * TILE * 256;
    #pragma unroll
    for (int h = 0; h < 2; h++) {
        #pragma unroll
        for (int t = 0; t < 4; t++) {
            int q   = tid + t * 256;          // 0..1023
            int row = q >> 3;
            int ch  = h * 8 + (q & 7);
            uint32_t soff = (uint32_t)row * 256u + ((uint32_t)(ch ^ (row & 7)) << 4);
            uint32_t goff = (uint32_t)row * 256u + (uint32_t)ch * 16u;
            CP16(sb + OFF_A + soff, Ag + goff);
            CP16(sb + OFF_B + soff, Bg + goff);
        }
        CP_COMMIT();
    }

    // prefetch norms while copies fly (prep data visible at kernel boundary)
    float n_pref = (tid < TILE)
        ? g_norm[bi * TILE + tid]
        : g_norm[bj * TILE + (tid - TILE)];

    // =============== per-warp MMA: 4x2 warps, 32x64 each ===================
    int wm = (wid & 3) * 32;
    int wn = (wid >> 2) * 64;

    float d[2][8][4];
    #pragma unroll
    for (int mt = 0; mt < 2; mt++)
        #pragma unroll
        for (int nt = 0; nt < 8; nt++)
            #pragma unroll
            for (int e = 0; e < 4; e++) d[mt][nt][e] = 0.f;

    uint32_t a_row  = (uint32_t)(wm + (lid & 15));
    uint32_t a_cbit = (uint32_t)(lid >> 4);
    uint32_t a_rl   = a_row & 7;
    uint32_t a_base0 = sb + OFF_A + a_row * 256u;
    uint32_t a_base1 = a_base0 + 16u * 256u;

    uint32_t b_row  = (uint32_t)(wn + (lid & 7) + ((lid & 16) >> 1));
    uint32_t b_cbit = (uint32_t)((lid >> 3) & 1);
    uint32_t b_rl   = b_row & 7;
    uint32_t b_base = sb + OFF_B + b_row * 256u;

    uint32_t af[2][2][4];
    uint32_t bf[2][8][2];

#define LOAD_A(kc, bufi) do {                                                   \
        uint32_t sc = ((uint32_t)(2 * (kc)) + a_cbit) ^ a_rl;                   \
        ldmatrix_x4(af[bufi][0][0], af[bufi][0][1], af[bufi][0][2],             \
                    af[bufi][0][3], a_base0 + (sc << 4));                       \
        ldmatrix_x4(af[bufi][1][0], af[bufi][1][1], af[bufi][1][2],             \
                    af[bufi][1][3], a_base1 + (sc << 4));                       \
    } while (0)

#define LOAD_B(kc, bufi) do {                                                   \
        uint32_t sc = ((uint32_t)(2 * (kc)) + b_cbit) ^ b_rl;                   \
        _Pragma("unroll")                                                       \
        for (int p = 0; p < 4; p++) {                                           \
            uint32_t addr = b_base + (uint32_t)p * (16u * 256u) + (sc << 4);    \
            ldmatrix_x4(bf[bufi][2 * p][0], bf[bufi][2 * p][1],                 \
                        bf[bufi][2 * p + 1][0], bf[bufi][2 * p + 1][1], addr);  \
        }                                                                       \
    } while (0)

    // first K-half landed; second still in flight
    CP_WAIT(1);
    __syncthreads();
    LOAD_A(0, 0);
    LOAD_B(0, 0);
    #pragma unroll
    for (int kc = 0; kc < 4; kc++) {
        int cur = kc & 1, nxt = cur ^ 1;
        if (kc < 3) { LOAD_A(kc + 1, nxt); LOAD_B(kc + 1, nxt); }
        #pragma unroll
        for (int mt = 0; mt < 2; mt++)
            #pragma unroll
            for (int nt = 0; nt < 8; nt++)
                mma_16816(d[mt][nt], af[cur][mt], bf[cur][nt]);
    }

    // second K-half landed
    CP_WAIT(0);
    __syncthreads();
    LOAD_A(4, 0);
    LOAD_B(4, 0);
    #pragma unroll
    for (int kc = 4; kc < 8; kc++) {
        int cur = kc & 1, nxt = cur ^ 1;
        if (kc < 7) { LOAD_A(kc + 1, nxt); LOAD_B(kc + 1, nxt); }
        #pragma unroll
        for (int mt = 0; mt < 2; mt++)
            #pragma unroll
            for (int nt = 0; nt < 8; nt++)
                mma_16816(d[mt][nt], af[cur][mt], bf[cur][nt]);
    }
#undef LOAD_A
#undef LOAD_B

    // =============== Wait for sigma (long done for most CTAs) =============
    if (tid == 0) spin_until((volatile int*)&g_flag2);
    __syncthreads();
    float c = __ldcg(&g_c);

    // const tiles from prefetched norms: ci = -ni*c, cj = -nj*c
    if (tid < TILE)
        reinterpret_cast<float*>(smem + OFF_CI)[tid] = -n_pref * c;
    else
        reinterpret_cast<float*>(smem + OFF_CJ)[tid - TILE] = -n_pref * c;
    __syncthreads();

    // epilogue: out = ex2(dot * 2c + ci + cj)
    float sc2 = 2.f * c;
    const float* cis = reinterpret_cast<const float*>(smem + OFF_CI);
    const float* cjs = reinterpret_cast<const float*>(smem + OFF_CJ);
    int quad = lid >> 2;
    int qt   = lid & 3;

    #pragma unroll
    for (int mt = 0; mt < 2; mt++) {
        #pragma unroll
        for (int half = 0; half < 2; half++) {
            int r  = wm + mt * 16 + quad + half * 8;
            float ci = cis[r];
            float* orow = out + (size_t)(bi * TILE + r) * NROWS + (size_t)bj * TILE + wn;
            #pragma unroll
            for (int nt = 0; nt < 8; nt++) {
                int col = nt * 8 + qt * 2;
                float e0 = fmaf(d[mt][nt][half * 2 + 0], sc2, ci + cjs[wn + col]);
                float e1 = fmaf(d[mt][nt][half * 2 + 1], sc2, ci + cjs[wn + col + 1]);
                *reinterpret_cast<float2*>(orow + col) = make_float2(ex2f(e0), ex2f(e1));
            }
        }
    }

    // =============== reset counters for next graph replay ==================
    __syncthreads();
    if (tid == 0) {
        if (atomicAdd(&g_ctr2, 1) == MAIN_CTAS - 1) {
            g_ctr3 = 0; g_ctr2 = 0; g_flag2 = 0;
        }
    }
}

// ---------------------------------------------------------------------------
// Launch
// ---------------------------------------------------------------------------
extern "C" void kernel_launch(void* const* d_in, const int* in_sizes, int n_in,
                              void* d_out, int out_size) {
    const float* X = (const float*)d_in[0];
    float* out = (float*)d_out;
    (void)in_sizes; (void)n_in; (void)out_size;

    cudaFuncSetAttribute(gauss_main_kernel,
                         cudaFuncAttributeMaxDynamicSharedMemorySize, SMEM_TOTAL);

    prep_kernel<<<PREP_BLOCKS, 256>>>(X);
    gauss_main_kernel<<<MAIN_CTAS, 256, SMEM_TOTAL>>>(out);
}